// round 5
// baseline (speedup 1.0000x reference)
#include <cuda_runtime.h>
#include <cstdint>

#define IMG_S 128
#define NPIX (IMG_S * IMG_S)
#define MAXF 4096
#define Z_NEAR 0.1f
#define Z_FAR 100.0f
#define SENTINEL 0xFFFFFFFFFFFFFFFFull

#define RB_BLOCKS 16
#define RB_THREADS 1024

// ---- scratch (no cudaMalloc allowed) ----
__device__ unsigned long long g_zbuf[NPIX];
__device__ float4 g_colors[MAXF];
__device__ float g_gray[NPIX];
__device__ int g_maxbits;                 // gray max as float bits (>=0)
__device__ float g_partmask[RB_BLOCKS];   // per-block mask partial sums
__device__ unsigned int g_ticket;

// ---------------------------------------------------------------------------
__global__ void k_init_zbuf() {
    int i = blockIdx.x * blockDim.x + threadIdx.x;
    if (i < NPIX) g_zbuf[i] = SENTINEL;
    if (i == 0) { g_maxbits = 0; g_ticket = 0; }
}

// ---------------------------------------------------------------------------
__device__ __forceinline__ float3 project_vert(float3 p,
                                               const float* __restrict__ R,
                                               const float* __restrict__ t,
                                               const float* __restrict__ K) {
    float vx = R[0] * p.x + R[1] * p.y + R[2] * p.z + t[0];
    float vy = R[3] * p.x + R[4] * p.y + R[5] * p.z + t[1];
    float vz = R[6] * p.x + R[7] * p.y + R[8] * p.z + t[2];
    float zd = vz + 1e-9f;
    float xn = vx / zd;
    float yn = vy / zd;
    float u = K[0] * xn + K[1] * yn + K[2];
    float v = K[3] * xn + K[4] * yn + K[5];
    float S = (float)IMG_S;
    float uu  = 2.0f * (u - S * 0.5f) / S;
    float vfl = S - v;
    float vvn = 2.0f * (vfl - S * 0.5f) / S;
    return make_float3(uu, vvn, vz);
}

// One warp per face: setup (redundant across lanes, cheap) + bbox raster.
__global__ void k_raster(const float* __restrict__ verts,
                         const int*   __restrict__ faces,
                         const float* __restrict__ tex,
                         const float* __restrict__ R,
                         const float* __restrict__ t,
                         const float* __restrict__ K,
                         const float* __restrict__ Ldir,
                         const float* __restrict__ idir_p,
                         const float* __restrict__ iamb_p,
                         int F) {
    int wid  = (blockIdx.x * blockDim.x + threadIdx.x) >> 5;
    int lane = threadIdx.x & 31;
    if (wid >= F) return;
    int f = wid;

    int i0 = faces[3 * f + 0];
    int i1 = faces[3 * f + 1];
    int i2 = faces[3 * f + 2];

    float3 A = make_float3(verts[3 * i0], verts[3 * i0 + 1], verts[3 * i0 + 2]);
    float3 B = make_float3(verts[3 * i1], verts[3 * i1 + 1], verts[3 * i1 + 2]);
    float3 C = make_float3(verts[3 * i2], verts[3 * i2 + 1], verts[3 * i2 + 2]);

    // ---- lighting (world space) ----
    float3 v10 = make_float3(A.x - B.x, A.y - B.y, A.z - B.z);
    float3 v12 = make_float3(C.x - B.x, C.y - B.y, C.z - B.z);
    float nx = v10.y * v12.z - v10.z * v12.y;
    float ny = v10.z * v12.x - v10.x * v12.z;
    float nz = v10.x * v12.y - v10.y * v12.x;
    float nrm = sqrtf(nx * nx + ny * ny + nz * nz);
    float inv = 1.0f / fmaxf(nrm, 1e-5f);
    nx *= inv; ny *= inv; nz *= inv;
    float cosv = fmaxf(0.0f, nx * Ldir[0] + ny * Ldir[1] + nz * Ldir[2]);
    float light = iamb_p[0] + idir_p[0] * cosv;
    if (lane == 0) {
        g_colors[f] = make_float4(tex[3 * f + 0] * light,
                                  tex[3 * f + 1] * light,
                                  tex[3 * f + 2] * light, 0.0f);
    }

    // ---- projection ----
    float3 p0 = project_vert(A, R, t, K);
    float3 p1 = project_vert(B, R, t, K);
    float3 p2 = project_vert(C, R, t, K);
    float z0 = p0.z, z1 = p1.z, z2 = p2.z;

    // ---- bbox in pixel space ----
    float Sf = (float)IMG_S;
    float minu = fminf(fminf(p0.x, p1.x), p2.x);
    float maxu = fmaxf(fmaxf(p0.x, p1.x), p2.x);
    float minv = fminf(fminf(p0.y, p1.y), p2.y);
    float maxv = fmaxf(fmaxf(p0.y, p1.y), p2.y);
    int x0 = max(0,         (int)floorf((minu * Sf + Sf - 1.0f) * 0.5f));
    int x1 = min(IMG_S - 1, (int)ceilf ((maxu * Sf + Sf - 1.0f) * 0.5f));
    int y0 = max(0,         (int)floorf((minv * Sf + Sf - 1.0f) * 0.5f));
    int y1 = min(IMG_S - 1, (int)ceilf ((maxv * Sf + Sf - 1.0f) * 0.5f));
    if (x0 > x1 || y0 > y1) return;

    int bw = x1 - x0 + 1;
    int bh = y1 - y0 + 1;
    int total = bw * bh;

    float e0x = p2.x - p1.x, e0y = p2.y - p1.y;   // edge(v1,v2)
    float e1x = p0.x - p2.x, e1y = p0.y - p2.y;   // edge(v2,v0)
    float e2x = p1.x - p0.x, e2y = p1.y - p0.y;   // edge(v0,v1)

    for (int i = lane; i < total; i += 32) {
        int x = x0 + (i % bw);
        int y = y0 + (i / bw);
        float px = (2.0f * x + 1.0f - Sf) / Sf;
        float py = (2.0f * y + 1.0f - Sf) / Sf;

        float w0 = e0x * (py - p1.y) - e0y * (px - p1.x);
        float w1 = e1x * (py - p2.y) - e1y * (px - p2.x);
        float w2 = e2x * (py - p0.y) - e2y * (px - p0.x);
        float area = w0 + w1 + w2;
        bool ok = fabsf(area) > 1e-10f;
        bool ins = ((w0 >= 0.0f && w1 >= 0.0f && w2 >= 0.0f) ||
                    (w0 <= 0.0f && w1 <= 0.0f && w2 <= 0.0f)) && ok;
        if (!ins) continue;
        float ia = 1.0f / area;
        float s = (w0 * ia) / z0 + (w1 * ia) / z1 + (w2 * ia) / z2 + 1e-12f;
        float zp = 1.0f / s;
        if (zp > Z_NEAR && zp < Z_FAR) {
            unsigned long long key =
                ((unsigned long long)__float_as_uint(zp) << 32) | (unsigned int)f;
            atomicMin(&g_zbuf[y * IMG_S + x], key);
        }
    }
}

// ---------------------------------------------------------------------------
// Fused: resolve z-buffer -> RGB/gray, global gray max (bitwise atomicMax),
// per-block mask partials, then the LAST block computes the loss.
// Deterministic: partials are per-block slots summed in fixed order; the
// final s1 pass reads identical data no matter which block runs it.
__global__ void __launch_bounds__(RB_THREADS)
k_resolve_loss(float* __restrict__ out,
               const float* __restrict__ mimg,
               const float* __restrict__ mask) {
    const int tid  = threadIdx.x;
    const int lane = tid & 31;
    const int wrp  = tid >> 5;
    const int p    = blockIdx.x * RB_THREADS + tid;   // exactly covers NPIX

    // ---- resolve ----
    unsigned long long key = g_zbuf[p];
    float r = 0.0f, g = 0.0f, b = 0.0f;
    if (key != SENTINEL) {
        int f = (int)(unsigned int)(key & 0xFFFFFFFFull);
        float4 c = g_colors[f];
        r = c.x; g = c.y; b = c.z;
    }
    out[1 + 0 * NPIX + p] = r;
    out[1 + 1 * NPIX + p] = g;
    out[1 + 2 * NPIX + p] = b;
    float gray = r + g + b;
    g_gray[p] = gray;

    // ---- block max + block mask partial ----
    float mx = gray;
    float ms = mask[p];
    #pragma unroll
    for (int o = 16; o > 0; o >>= 1) {
        mx = fmaxf(mx, __shfl_down_sync(0xFFFFFFFFu, mx, o));
        ms += __shfl_down_sync(0xFFFFFFFFu, ms, o);
    }
    __shared__ float smx[32], sms[32];
    if (lane == 0) { smx[wrp] = mx; sms[wrp] = ms; }
    __syncthreads();
    __shared__ bool is_last;
    if (tid == 0) {
        float m = smx[0], s = sms[0];
        #pragma unroll
        for (int w = 1; w < 32; w++) { m = fmaxf(m, smx[w]); s += sms[w]; }
        atomicMax(&g_maxbits, __float_as_int(m));
        g_partmask[blockIdx.x] = s;
        __threadfence();
        unsigned int t = atomicAdd(&g_ticket, 1u);
        is_last = (t == RB_BLOCKS - 1);
    }
    __syncthreads();
    if (!is_last) return;

    // ---- last block: final loss ----
    float maxv = __int_as_float(g_maxbits);
    const float4* g4 = (const float4*)g_gray;
    const float4* m4 = (const float4*)mimg;

    float s1 = 0.0f;
    #pragma unroll
    for (int i = tid; i < NPIX / 4; i += RB_THREADS) {
        float4 gg = g4[i];
        float4 mm = m4[i];
        float d0 = gg.x / maxv - mm.x;
        float d1 = gg.y / maxv - mm.y;
        float d2 = gg.z / maxv - mm.z;
        float d3 = gg.w / maxv - mm.w;
        s1 += d0 * d0 + d1 * d1 + d2 * d2 + d3 * d3;
    }
    #pragma unroll
    for (int o = 16; o > 0; o >>= 1)
        s1 += __shfl_down_sync(0xFFFFFFFFu, s1, o);
    __shared__ float sa[32];
    if (lane == 0) sa[wrp] = s1;
    __syncthreads();
    if (tid == 0) {
        float S1 = sa[0];
        #pragma unroll
        for (int w = 1; w < 32; w++) S1 += sa[w];
        float S2 = g_partmask[0];
        #pragma unroll
        for (int w = 1; w < RB_BLOCKS; w++) S2 += g_partmask[w];
        out[0] = S1 / S2;
    }
}

// ---------------------------------------------------------------------------
extern "C" void kernel_launch(void* const* d_in, const int* in_sizes, int n_in,
                              void* d_out, int out_size) {
    const float* verts = (const float*)d_in[0];
    const int*   faces = (const int*)  d_in[1];
    const float* tex   = (const float*)d_in[2];
    const float* R     = (const float*)d_in[3];
    const float* t     = (const float*)d_in[4];
    const float* K     = (const float*)d_in[5];
    const float* mimg  = (const float*)d_in[6];
    const float* mask  = (const float*)d_in[7];
    const float* Ldir  = (const float*)d_in[8];
    const float* idir  = (const float*)d_in[9];
    const float* iamb  = (const float*)d_in[10];
    float* out = (float*)d_out;

    int F = in_sizes[1] / 3;

    k_init_zbuf<<<(NPIX + 255) / 256, 256>>>();
    int threads = 128;
    int blocks  = (F * 32 + threads - 1) / threads;
    k_raster<<<blocks, threads>>>(verts, faces, tex, R, t, K, Ldir, idir, iamb, F);
    k_resolve_loss<<<RB_BLOCKS, RB_THREADS>>>(out, mimg, mask);
}